// round 8
// baseline (speedup 1.0000x reference)
#include <cuda_runtime.h>
#include <math.h>

#define N_ATOMS 4096
#define NG      12
#define N_GRID  1728
#define N_TOT   5824
#define HID     256
#define KNBR    32
#define NRBF    64
#define CUTOFF  12.0f
#define RBF_W   (CUTOFF / (float)NRBF)
#define RBF_STEP (CUTOFF / 63.0f)
#define BIGD    1e9f
#define VNODE_Z 120
#define NEMB    125
#define MAXC    1536
#define NBIN    128
#define BINCAP  256
#define U64MAX  0xFFFFFFFFFFFFFFFFull
#define NCELL   8
#define NCELL3  512
#define CSIZE   5.0f

// ---------------- device scratch ----------------
__device__ float4 g_pos4[N_TOT];
__device__ int    g_valid[N_TOT];
__device__ int    g_z[N_TOT];
__device__ int    g_nbr[N_TOT * KNBR];
__device__ float  g_dedge[N_TOT * KNBR];
__device__ float  g_eW1[NEMB * HID];
__device__ float  g_WW[NRBF * HID];
__device__ float  g_S[N_TOT * HID];
__device__ int    g_cnt[N_TOT];
__device__ int    g_cellcnt[NCELL3];
__device__ int    g_cellstart[NCELL3];
__device__ int    g_cellnodes[N_TOT];

__device__ __forceinline__ int cell_of(float x, float y, float z) {
    int ix = min(NCELL - 1, max(0, (int)(x / CSIZE)));
    int iy = min(NCELL - 1, max(0, (int)(y / CSIZE)));
    int iz = min(NCELL - 1, max(0, (int)(z / CSIZE)));
    return (ix * NCELL + iy) * NCELL + iz;
}

__device__ __forceinline__ float cell_mind2(int c, float px, float py, float pz) {
    int ix = c / (NCELL * NCELL), iy = (c / NCELL) % NCELL, iz = c % NCELL;
    float lx = ix * CSIZE, ly = iy * CSIZE, lz = iz * CSIZE;
    float dx = fmaxf(0.0f, fmaxf(lx - px, px - (lx + CSIZE)));
    float dy = fmaxf(0.0f, fmaxf(ly - py, py - (ly + CSIZE)));
    float dz = fmaxf(0.0f, fmaxf(lz - pz, pz - (lz + CSIZE)));
    return dx * dx + dy * dy + dz * dz;
}

// ---------------- kernel 1: setup + zero cell counts ----------------
__global__ void k_setup(const float* __restrict__ pos,
                        const int* __restrict__ an,
                        const float* __restrict__ cell) {
    int i = blockIdx.x * blockDim.x + threadIdx.x;
    if (i < NCELL3) g_cellcnt[i] = 0;
    if (i >= N_TOT) return;
    float x, y, z;
    if (i < N_ATOMS) {
        x = pos[3 * i + 0]; y = pos[3 * i + 1]; z = pos[3 * i + 2];
        g_valid[i] = 1;
        g_z[i] = an[i];
    } else {
        int g = i - N_ATOMS;
        int ix = g / (NG * NG), iy = (g / NG) % NG, iz = g % NG;
        float f0 = (float)ix / (float)NG;
        float f1 = (float)iy / (float)NG;
        float f2 = (float)iz / (float)NG;
        x = f0 * cell[0] + f1 * cell[3] + f2 * cell[6];
        y = f0 * cell[1] + f1 * cell[4] + f2 * cell[7];
        z = f0 * cell[2] + f1 * cell[5] + f2 * cell[8];
        g_z[i] = VNODE_Z;
    }
    g_pos4[i] = make_float4(x, y, z, x * x + y * y + z * z);
}

__global__ void k_cellcount() {
    int i = blockIdx.x * blockDim.x + threadIdx.x;
    if (i >= N_TOT) return;
    float4 p = g_pos4[i];
    atomicAdd(&g_cellcnt[cell_of(p.x, p.y, p.z)], 1);
}

// single block: scan + scatter
__global__ void __launch_bounds__(NCELL3) k_cellbuild() {
    __shared__ int tmp[NCELL3];
    __shared__ int fill[NCELL3];
    int t = threadIdx.x;
    int v = g_cellcnt[t];
    tmp[t] = v;
    __syncthreads();
    for (int off = 1; off < NCELL3; off <<= 1) {
        int x = (t >= off) ? tmp[t - off] : 0;
        __syncthreads();
        tmp[t] += x;
        __syncthreads();
    }
    int excl = tmp[t] - v;
    g_cellstart[t] = excl;
    fill[t] = excl;
    __syncthreads();
    for (int i = t; i < N_TOT; i += NCELL3) {
        float4 p = g_pos4[i];
        int pp = atomicAdd(&fill[cell_of(p.x, p.y, p.z)], 1);
        g_cellnodes[pp] = i;
    }
}

// ---------------- kernel 2: vnode repulsion mask (warp-per-vnode) ----------------
__global__ void __launch_bounds__(256) k_vmask() {
    int w = threadIdx.x >> 5, lane = threadIdx.x & 31;
    int i = N_ATOMS + blockIdx.x * 8 + w;
    if (i >= N_TOT) return;
    float4 p = g_pos4[i];
    float m = 3e38f;
    for (int c = lane; c < NCELL3; c += 32) {
        int cnt = g_cellcnt[c];
        if (cnt > 0 && cell_mind2(c, p.x, p.y, p.z) <= 4.01f) {
            int st = g_cellstart[c];
            for (int t = 0; t < cnt; t++) {
                int j = g_cellnodes[st + t];
                if (j < N_ATOMS) {
                    float4 qq = g_pos4[j];
                    float d2 = p.w + qq.w - 2.0f * (p.x * qq.x + p.y * qq.y + p.z * qq.z);
                    m = fminf(m, d2);
                }
            }
        }
    }
    #pragma unroll
    for (int o = 16; o; o >>= 1) m = fminf(m, __shfl_xor_sync(0xffffffffu, m, o));
    if (lane == 0) g_valid[i] = (m >= 4.0f) ? 1 : 0;
}

// ---------------- kernel 3: merged precompute ----------------
__global__ void __launch_bounds__(256) k_pre(const float* __restrict__ embed,
                                             const float* __restrict__ Wrbf,
                                             const float* __restrict__ W1) {
    int r = blockIdx.x, c = threadIdx.x;
    const float* A = (r < NEMB) ? (embed + (size_t)r * HID)
                                : (Wrbf + (size_t)(r - NEMB) * HID);
    float a0 = 0.f, a1 = 0.f, a2 = 0.f, a3 = 0.f;
    #pragma unroll 8
    for (int k = 0; k < HID; k += 4) {
        a0 += A[k + 0] * W1[(k + 0) * HID + c];
        a1 += A[k + 1] * W1[(k + 1) * HID + c];
        a2 += A[k + 2] * W1[(k + 2) * HID + c];
        a3 += A[k + 3] * W1[(k + 3) * HID + c];
    }
    float acc = (a0 + a1) + (a2 + a3);
    if (r < NEMB) g_eW1[r * HID + c] = acc;
    else          g_WW[(r - NEMB) * HID + c] = acc;
}

// ---------------- kernel 4: cell-accelerated top-K ----------------
__global__ void __launch_bounds__(256) k_topk() {
    int i = blockIdx.x, tid = threadIdx.x;
    int w = tid >> 5, lane = tid & 31;
    __shared__ unsigned long long cand[MAXC];
    __shared__ unsigned long long binbuf[BINCAP];
    __shared__ unsigned long long sel[KNBR];
    __shared__ int hist[NBIN];
    __shared__ int pcell[160];
    __shared__ int ncand, nsel, nbin, s_B, npass_s;
    if (!g_valid[i]) {
        if (tid < KNBR) { g_nbr[i * KNBR + tid] = 0; g_dedge[i * KNBR + tid] = BIGD; }
        return;
    }
    if (tid == 0) { ncand = 0; nsel = 0; nbin = 0; npass_s = 0; }
    if (tid < NBIN) hist[tid] = 0;
    __syncthreads();

    float4 p = g_pos4[i];

    for (int c = tid; c < NCELL3; c += 256) {
        if (g_cellcnt[c] > 0 && cell_mind2(c, p.x, p.y, p.z) <= 145.5f) {
            int q = atomicAdd(&npass_s, 1);
            if (q < 160) pcell[q] = c;
        }
    }
    __syncthreads();
    int np = min(npass_s, 160);

    for (int q = w; q < np; q += 8) {
        int pc = pcell[q];
        int st = g_cellstart[pc], cnt = g_cellcnt[pc];
        int cr = (cnt + 31) & ~31;
        for (int t = lane; t < cr; t += 32) {
            bool keep = false;
            float d2 = 0.0f;
            int j = -1;
            if (t < cnt) {
                j = g_cellnodes[st + t];
                float4 qq = g_pos4[j];
                d2 = p.w + qq.w - 2.0f * (p.x * qq.x + p.y * qq.y + p.z * qq.z);
                keep = (d2 <= 145.0f) && (j != i) && (g_valid[j] != 0);
            }
            unsigned m = __ballot_sync(0xffffffffu, keep);
            int cpos = 0;
            if (lane == 0) cpos = m ? atomicAdd(&ncand, __popc(m)) : 0;
            cpos = __shfl_sync(0xffffffffu, cpos, 0);
            if (keep) {
                int off = cpos + __popc(m & ((1u << lane) - 1u));
                if (off < MAXC)
                    cand[off] = ((unsigned long long)__float_as_uint(fmaxf(d2, 0.0f)) << 32)
                                | (unsigned)j;
            }
        }
    }
    __syncthreads();
    int nc = min(ncand, MAXC);

    if (nc <= KNBR) {
        if (tid < KNBR) sel[tid] = (tid < nc) ? cand[tid] : U64MAX;
        __syncthreads();
    } else {
        for (int idx = tid; idx < nc; idx += 256) {
            float d2 = __uint_as_float((unsigned)(cand[idx] >> 32));
            int b = min(NBIN - 1, (int)(d2 * ((float)NBIN / 145.0f)));
            atomicAdd(&hist[b], 1);
        }
        __syncthreads();
        if (tid == 0) {
            int c = 0, B = NBIN - 1;
            for (int b = 0; b < NBIN; b++) {
                if (c + hist[b] >= KNBR) { B = b; break; }
                c += hist[b];
            }
            s_B = B;
        }
        __syncthreads();
        int B = s_B;
        for (int idx = tid; idx < nc; idx += 256) {
            unsigned long long key = cand[idx];
            float d2 = __uint_as_float((unsigned)(key >> 32));
            int b = min(NBIN - 1, (int)(d2 * ((float)NBIN / 145.0f)));
            if (b < B) {
                sel[atomicAdd(&nsel, 1)] = key;
            } else if (b == B) {
                int pp = atomicAdd(&nbin, 1);
                if (pp < BINCAP) binbuf[pp] = key;
            }
        }
        __syncthreads();
        if (tid == 0) {
            int have = nsel;
            int m = KNBR - have;
            int bc = min(nbin, BINCAP);
            for (int s = 0; s < m; s++) {
                unsigned long long best = U64MAX;
                int bi = -1;
                for (int t = 0; t < bc; t++)
                    if (binbuf[t] < best) { best = binbuf[t]; bi = t; }
                if (bi >= 0) binbuf[bi] = U64MAX;
                sel[have + s] = best;
            }
        }
        __syncthreads();
    }

    if (tid < 32) {
        unsigned long long v = sel[tid];
        #pragma unroll
        for (int k = 2; k <= 32; k <<= 1) {
            #pragma unroll
            for (int j = k >> 1; j > 0; j >>= 1) {
                unsigned long long o = __shfl_xor_sync(0xffffffffu, v, j);
                bool up = ((tid & k) == 0);
                bool lower = ((tid & j) == 0);
                unsigned long long mn = min(v, o), mx = max(v, o);
                v = (up == lower) ? mn : mx;
            }
        }
        if (v == U64MAX) {
            g_nbr[i * KNBR + tid] = 0;
            g_dedge[i * KNBR + tid] = BIGD;
        } else {
            g_nbr[i * KNBR + tid] = (int)(v & 0xFFFFFFFFull);
            float d2 = __uint_as_float((unsigned)(v >> 32));
            g_dedge[i * KNBR + tid] = sqrtf(fmaxf(d2, 1e-12f));
        }
    }
}

// ---------------- kernel 5: per-edge messages ----------------
// Warp w: edge group g=w&3 (edges 8g..8g+7), col half h=w>>2 (cols 128h..128h+127).
// Lane l owns float4 at col 128h+4l. Halves redundant g_WW traffic vs all-col warps.
__global__ void __launch_bounds__(256) k_msg(const float* __restrict__ b1) {
    int i = blockIdx.x, tid = threadIdx.x;
    if (!g_valid[i]) {
        g_S[(size_t)i * HID + tid] = 0.0f;
        if (tid == 0) g_cnt[i] = 0;
        return;
    }
    __shared__ float Rs[KNBR * NRBF];      // 8 KB
    __shared__ float part[8 * 128];        // 4 KB  [warp][col-in-half]
    __shared__ int   nbr_s[KNBR];
    __shared__ float de_s[KNBR];
    if (tid < KNBR) {
        nbr_s[tid] = g_nbr[i * KNBR + tid];
        de_s[tid]  = g_dedge[i * KNBR + tid];
    }
    __syncthreads();
    for (int idx = tid; idx < KNBR * NRBF; idx += 256) {
        int e = idx >> 6, r = idx & 63;
        float cr = (float)r * RBF_STEP;
        float t = (de_s[e] - cr) * (1.0f / RBF_W);
        float t2 = t * t;
        Rs[idx] = (t2 < 32.0f) ? __expf(-0.5f * t2) : 0.0f;
    }
    if (tid == 0) {
        int c = 0;
        for (int e = 0; e < KNBR; e++) if (de_s[e] <= CUTOFF) c++;
        g_cnt[i] = c;
    }
    __syncthreads();

    int w = tid >> 5, l = tid & 31;
    int g = w & 3, h = w >> 2;           // edge group, col half
    int fo = h * 32 + l;                  // float4 offset within row
    int zi = g_z[i];
    float4 eif = ((const float4*)(g_eW1 + zi * HID))[fo];
    float4 b1f = ((const float4*)b1)[fo];
    float4 base = make_float4(eif.x + b1f.x, eif.y + b1f.y,
                              eif.z + b1f.z, eif.w + b1f.w);

    float4 acc[8];
    #pragma unroll
    for (int e = 0; e < 8; e++) {
        int zn = g_z[nbr_s[8 * g + e]];
        float4 en = ((const float4*)(g_eW1 + zn * HID))[fo];
        acc[e] = make_float4(base.x + en.x, base.y + en.y,
                             base.z + en.z, base.w + en.w);
    }

    // active RBF window over this group's 8 edges (sorted ascending)
    float dmin = 3e38f, dmax = -1.0f;
    #pragma unroll
    for (int e = 0; e < 8; e++) {
        float d = de_s[8 * g + e];
        if (d <= CUTOFF) { dmin = fminf(dmin, d); dmax = fmaxf(dmax, d); }
    }
    if (dmax >= 0.0f) {
        int kmin = max(0,  (int)ceilf ((dmin - 1.0607f) * (1.0f / RBF_STEP)));
        int kmax = min(63, (int)floorf((dmax + 1.0607f) * (1.0f / RBF_STEP)));
        const float* rs_g = Rs + (8 * g) * NRBF;
        for (int k = kmin; k <= kmax; k++) {
            float4 wv = ((const float4*)(g_WW + k * HID))[fo];
            #pragma unroll
            for (int e = 0; e < 8; e++) {
                float rv = rs_g[e * NRBF + k];
                acc[e].x += rv * wv.x; acc[e].y += rv * wv.y;
                acc[e].z += rv * wv.z; acc[e].w += rv * wv.w;
            }
        }
    }

    // silu + cutoff mask + sum over the 8 edges
    float4 c0 = make_float4(0, 0, 0, 0);
    #pragma unroll
    for (int e = 0; e < 8; e++) {
        if (de_s[8 * g + e] <= CUTOFF) {
            c0.x += __fdividef(acc[e].x, 1.0f + __expf(-acc[e].x));
            c0.y += __fdividef(acc[e].y, 1.0f + __expf(-acc[e].y));
            c0.z += __fdividef(acc[e].z, 1.0f + __expf(-acc[e].z));
            c0.w += __fdividef(acc[e].w, 1.0f + __expf(-acc[e].w));
        }
    }
    ((float4*)(part + w * 128))[l] = c0;
    __syncthreads();
    // reduce 4 edge-groups per col-half: warps {4h..4h+3} cover global col tid
    {
        int hh = tid >> 7, cc = tid & 127;
        float s = part[(4 * hh + 0) * 128 + cc] + part[(4 * hh + 1) * 128 + cc]
                + part[(4 * hh + 2) * 128 + cc] + part[(4 * hh + 3) * 128 + cc];
        g_S[(size_t)i * HID + tid] = s;
    }
}

// ---------------- kernel 6: feat = h + S@W2 + cnt*b2, plus masks ----------------
__global__ void __launch_bounds__(256) k_final(const float* __restrict__ embed,
                                               const float* __restrict__ W2,
                                               const float* __restrict__ b2,
                                               float* __restrict__ out,
                                               int out_size) {
    int base = blockIdx.x * 32;
    int tid = threadIdx.x, w = tid >> 5, l = tid & 31;
    __shared__ float Ssm[32 * HID];
    for (int idx = tid; idx < 32 * HID; idx += 256)
        Ssm[idx] = g_S[(size_t)(base + (idx >> 8)) * HID + (idx & 255)];
    __syncthreads();

    float4 y0[4], y1[4];
    #pragma unroll
    for (int rr = 0; rr < 4; rr++) {
        y0[rr] = make_float4(0, 0, 0, 0);
        y1[rr] = make_float4(0, 0, 0, 0);
    }
    #pragma unroll 4
    for (int k = 0; k < HID; k++) {
        const float4* w2row = (const float4*)(W2 + k * HID);
        float4 wa = w2row[l], wb = w2row[32 + l];
        #pragma unroll
        for (int rr = 0; rr < 4; rr++) {
            float sv = Ssm[(4 * w + rr) * HID + k];
            y0[rr].x += sv * wa.x; y0[rr].y += sv * wa.y;
            y0[rr].z += sv * wa.z; y0[rr].w += sv * wa.w;
            y1[rr].x += sv * wb.x; y1[rr].y += sv * wb.y;
            y1[rr].z += sv * wb.z; y1[rr].w += sv * wb.w;
        }
    }
    const float4* b24 = (const float4*)b2;
    float4 ba = b24[l], bb = b24[32 + l];
    #pragma unroll
    for (int rr = 0; rr < 4; rr++) {
        int n = base + 4 * w + rr;
        int valid = g_valid[n];
        float cnt = (float)g_cnt[n];
        const float4* e4 = (const float4*)(embed + (size_t)g_z[n] * HID);
        float4 ea = e4[l], eb = e4[32 + l];
        float4 oa = make_float4(0, 0, 0, 0), ob = make_float4(0, 0, 0, 0);
        if (valid) {
            oa = make_float4(ea.x + y0[rr].x + cnt * ba.x,
                             ea.y + y0[rr].y + cnt * ba.y,
                             ea.z + y0[rr].z + cnt * ba.z,
                             ea.w + y0[rr].w + cnt * ba.w);
            ob = make_float4(eb.x + y1[rr].x + cnt * bb.x,
                             eb.y + y1[rr].y + cnt * bb.y,
                             eb.z + y1[rr].z + cnt * bb.z,
                             eb.w + y1[rr].w + cnt * bb.w);
        }
        ((float4*)(out + (size_t)n * HID))[l]      = oa;
        ((float4*)(out + (size_t)n * HID))[32 + l] = ob;
    }
    if (tid < 32 && out_size >= N_TOT * HID + 2 * N_TOT) {
        int n = base + tid;
        out[N_TOT * HID + n] = (n >= N_ATOMS && g_valid[n]) ? 1.0f : 0.0f;
        out[N_TOT * HID + N_TOT + n] = (n < N_ATOMS) ? 1.0f : 0.0f;
    }
}

// ---------------- launcher ----------------
extern "C" void kernel_launch(void* const* d_in, const int* in_sizes, int n_in,
                              void* d_out, int out_size) {
    const float* pos   = (const float*)d_in[0];
    const int*   an    = (const int*)  d_in[1];
    const float* cell  = (const float*)d_in[2];
    const float* embed = (const float*)d_in[3];
    const float* Wrbf  = (const float*)d_in[4];
    const float* W1    = (const float*)d_in[5];
    const float* b1    = (const float*)d_in[6];
    const float* W2    = (const float*)d_in[7];
    const float* b2    = (const float*)d_in[8];
    float* out = (float*)d_out;

    k_setup<<<(N_TOT + 255) / 256, 256>>>(pos, an, cell);
    k_cellcount<<<(N_TOT + 255) / 256, 256>>>();
    k_cellbuild<<<1, NCELL3>>>();
    k_vmask<<<(N_GRID + 7) / 8, 256>>>();
    k_pre<<<NEMB + NRBF, 256>>>(embed, Wrbf, W1);
    k_topk<<<N_TOT, 256>>>();
    k_msg<<<N_TOT, 256>>>(b1);
    k_final<<<N_TOT / 32, 256>>>(embed, W2, b2, out, out_size);
}

// round 9
// speedup vs baseline: 1.1957x; 1.1957x over previous
#include <cuda_runtime.h>
#include <math.h>

#define N_ATOMS 4096
#define NG      12
#define N_GRID  1728
#define N_TOT   5824
#define HID     256
#define KNBR    32
#define NRBF    64
#define CUTOFF  12.0f
#define RBF_W   (CUTOFF / (float)NRBF)
#define RBF_STEP (CUTOFF / 63.0f)
#define BIGD    1e9f
#define VNODE_Z 120
#define NEMB    125
#define MAXC    1536
#define NBIN    128
#define BINCAP  256
#define U64MAX  0xFFFFFFFFFFFFFFFFull
#define NCELL   8
#define NCELL3  512
#define CSIZE   5.0f

// ---------------- device scratch ----------------
__device__ float4 g_pos4[N_TOT];
__device__ int    g_valid[N_TOT];
__device__ int    g_z[N_TOT];
__device__ int    g_nbr[N_TOT * KNBR];
__device__ float  g_dedge[N_TOT * KNBR];
__device__ float  g_eW1[NEMB * HID];
__device__ float  g_WW[NRBF * HID];
__device__ float  g_S[N_TOT * HID];
__device__ int    g_cnt[N_TOT];
__device__ int    g_cellcnt[NCELL3];
__device__ int    g_cellstart[NCELL3];
__device__ int    g_cellnodes[N_TOT];

__device__ __forceinline__ int cell_of(float x, float y, float z) {
    int ix = min(NCELL - 1, max(0, (int)(x / CSIZE)));
    int iy = min(NCELL - 1, max(0, (int)(y / CSIZE)));
    int iz = min(NCELL - 1, max(0, (int)(z / CSIZE)));
    return (ix * NCELL + iy) * NCELL + iz;
}

__device__ __forceinline__ float cell_mind2(int c, float px, float py, float pz) {
    int ix = c / (NCELL * NCELL), iy = (c / NCELL) % NCELL, iz = c % NCELL;
    float lx = ix * CSIZE, ly = iy * CSIZE, lz = iz * CSIZE;
    float dx = fmaxf(0.0f, fmaxf(lx - px, px - (lx + CSIZE)));
    float dy = fmaxf(0.0f, fmaxf(ly - py, py - (ly + CSIZE)));
    float dz = fmaxf(0.0f, fmaxf(lz - pz, pz - (lz + CSIZE)));
    return dx * dx + dy * dy + dz * dz;
}

// ---------------- kernel 1: setup ----------------
__global__ void k_setup(const float* __restrict__ pos,
                        const int* __restrict__ an,
                        const float* __restrict__ cell) {
    int i = blockIdx.x * blockDim.x + threadIdx.x;
    if (i >= N_TOT) return;
    float x, y, z;
    if (i < N_ATOMS) {
        x = pos[3 * i + 0]; y = pos[3 * i + 1]; z = pos[3 * i + 2];
        g_valid[i] = 1;
        g_z[i] = an[i];
    } else {
        int g = i - N_ATOMS;
        int ix = g / (NG * NG), iy = (g / NG) % NG, iz = g % NG;
        float f0 = (float)ix / (float)NG;
        float f1 = (float)iy / (float)NG;
        float f2 = (float)iz / (float)NG;
        x = f0 * cell[0] + f1 * cell[3] + f2 * cell[6];
        y = f0 * cell[1] + f1 * cell[4] + f2 * cell[7];
        z = f0 * cell[2] + f1 * cell[5] + f2 * cell[8];
        g_z[i] = VNODE_Z;
    }
    g_pos4[i] = make_float4(x, y, z, x * x + y * y + z * z);
}

// ---------------- single block: count + scan + scatter ----------------
__global__ void __launch_bounds__(NCELL3) k_cellbuild() {
    __shared__ int cnt[NCELL3];
    __shared__ int tmp[NCELL3];
    __shared__ int fill[NCELL3];
    int t = threadIdx.x;
    cnt[t] = 0;
    __syncthreads();
    for (int i = t; i < N_TOT; i += NCELL3) {
        float4 p = g_pos4[i];
        atomicAdd(&cnt[cell_of(p.x, p.y, p.z)], 1);
    }
    __syncthreads();
    int v = cnt[t];
    tmp[t] = v;
    __syncthreads();
    for (int off = 1; off < NCELL3; off <<= 1) {
        int x = (t >= off) ? tmp[t - off] : 0;
        __syncthreads();
        tmp[t] += x;
        __syncthreads();
    }
    int excl = tmp[t] - v;
    g_cellstart[t] = excl;
    g_cellcnt[t] = v;
    fill[t] = excl;
    __syncthreads();
    for (int i = t; i < N_TOT; i += NCELL3) {
        float4 p = g_pos4[i];
        int pp = atomicAdd(&fill[cell_of(p.x, p.y, p.z)], 1);
        g_cellnodes[pp] = i;
    }
}

// ---------------- kernel 2: vnode repulsion mask (R7 version) ----------------
__global__ void __launch_bounds__(256) k_vmask() {
    int i = N_ATOMS + blockIdx.x;
    int tid = threadIdx.x, w = tid >> 5, lane = tid & 31;
    __shared__ int pcell[64];
    __shared__ int npass_s;
    __shared__ float wm[8];
    if (tid == 0) npass_s = 0;
    __syncthreads();
    float4 p = g_pos4[i];
    for (int c = tid; c < NCELL3; c += 256) {
        if (g_cellcnt[c] > 0 && cell_mind2(c, p.x, p.y, p.z) <= 4.01f) {
            int q = atomicAdd(&npass_s, 1);
            if (q < 64) pcell[q] = c;
        }
    }
    __syncthreads();
    int np = min(npass_s, 64);
    float m = 3e38f;
    for (int q = w; q < np; q += 8) {
        int pc = pcell[q];
        int st = g_cellstart[pc], cnt = g_cellcnt[pc];
        for (int t = lane; t < cnt; t += 32) {
            int j = g_cellnodes[st + t];
            if (j < N_ATOMS) {
                float4 qq = g_pos4[j];
                float d2 = p.w + qq.w - 2.0f * (p.x * qq.x + p.y * qq.y + p.z * qq.z);
                m = fminf(m, d2);
            }
        }
    }
    #pragma unroll
    for (int o = 16; o; o >>= 1) m = fminf(m, __shfl_xor_sync(0xffffffffu, m, o));
    if (lane == 0) wm[w] = m;
    __syncthreads();
    if (tid == 0) {
        float b = wm[0];
        #pragma unroll
        for (int ww = 1; ww < 8; ww++) b = fminf(b, wm[ww]);
        g_valid[i] = (b >= 4.0f) ? 1 : 0;
    }
}

// ---------------- kernel 3: merged precompute (8 accumulators) ----------------
__global__ void __launch_bounds__(256) k_pre(const float* __restrict__ embed,
                                             const float* __restrict__ Wrbf,
                                             const float* __restrict__ W1) {
    int r = blockIdx.x, c = threadIdx.x;
    const float* A = (r < NEMB) ? (embed + (size_t)r * HID)
                                : (Wrbf + (size_t)(r - NEMB) * HID);
    float a0 = 0.f, a1 = 0.f, a2 = 0.f, a3 = 0.f;
    float a4 = 0.f, a5 = 0.f, a6 = 0.f, a7 = 0.f;
    #pragma unroll 4
    for (int k = 0; k < HID; k += 8) {
        a0 += A[k + 0] * W1[(k + 0) * HID + c];
        a1 += A[k + 1] * W1[(k + 1) * HID + c];
        a2 += A[k + 2] * W1[(k + 2) * HID + c];
        a3 += A[k + 3] * W1[(k + 3) * HID + c];
        a4 += A[k + 4] * W1[(k + 4) * HID + c];
        a5 += A[k + 5] * W1[(k + 5) * HID + c];
        a6 += A[k + 6] * W1[(k + 6) * HID + c];
        a7 += A[k + 7] * W1[(k + 7) * HID + c];
    }
    float acc = ((a0 + a1) + (a2 + a3)) + ((a4 + a5) + (a6 + a7));
    if (r < NEMB) g_eW1[r * HID + c] = acc;
    else          g_WW[(r - NEMB) * HID + c] = acc;
}

// ---------------- kernel 4: top-K via contiguous z-column ranges ----------------
__global__ void __launch_bounds__(256) k_topk() {
    int i = blockIdx.x, tid = threadIdx.x;
    int w = tid >> 5, lane = tid & 31;
    __shared__ unsigned long long cand[MAXC];
    __shared__ unsigned long long binbuf[BINCAP];
    __shared__ unsigned long long sel[KNBR];
    __shared__ int hist[NBIN];
    __shared__ int rs[64], rl[64];
    __shared__ int ncand, nsel, nbin, s_B, nrange;
    if (!g_valid[i]) {
        if (tid < KNBR) { g_nbr[i * KNBR + tid] = 0; g_dedge[i * KNBR + tid] = BIGD; }
        return;
    }
    if (tid == 0) { ncand = 0; nsel = 0; nbin = 0; nrange = 0; }
    if (tid < NBIN) hist[tid] = 0;
    __syncthreads();

    float4 p = g_pos4[i];

    // --- phase A0: per-(ix,iy) column, passing z-cells form a contiguous range ---
    if (tid < 64) {
        int ix = tid >> 3, iy = tid & 7;
        float lx = ix * CSIZE, ly = iy * CSIZE;
        float dx = fmaxf(0.0f, fmaxf(lx - p.x, p.x - (lx + CSIZE)));
        float dy = fmaxf(0.0f, fmaxf(ly - p.y, p.y - (ly + CSIZE)));
        float dxy2 = dx * dx + dy * dy;
        if (dxy2 <= 145.5f) {
            float rem = sqrtf(145.5f - dxy2);
            int z0 = max(0,         (int)floorf((p.z - rem) * (1.0f / CSIZE)));
            int z1 = min(NCELL - 1, (int)floorf((p.z + rem) * (1.0f / CSIZE)));
            int c0 = tid * NCELL + z0, c1 = tid * NCELL + z1;
            int st = g_cellstart[c0];
            int en = g_cellstart[c1] + g_cellcnt[c1];
            if (en > st) {
                int q = atomicAdd(&nrange, 1);
                rs[q] = st; rl[q] = en - st;
            }
        }
    }
    __syncthreads();
    int np = nrange;

    // --- phase A: warp-per-range sweep + compaction + fused histogram ---
    for (int q = w; q < np; q += 8) {
        int st = rs[q], len = rl[q];
        int cr = (len + 31) & ~31;
        for (int t = lane; t < cr; t += 32) {
            bool keep = false;
            float d2 = 0.0f;
            int j = -1;
            if (t < len) {
                j = g_cellnodes[st + t];
                float4 qq = g_pos4[j];
                d2 = p.w + qq.w - 2.0f * (p.x * qq.x + p.y * qq.y + p.z * qq.z);
                keep = (d2 <= 145.0f) && (j != i) && (g_valid[j] != 0);
            }
            unsigned m = __ballot_sync(0xffffffffu, keep);
            int cpos = 0;
            if (lane == 0) cpos = m ? atomicAdd(&ncand, __popc(m)) : 0;
            cpos = __shfl_sync(0xffffffffu, cpos, 0);
            if (keep) {
                float d2c = fmaxf(d2, 0.0f);
                int off = cpos + __popc(m & ((1u << lane) - 1u));
                if (off < MAXC)
                    cand[off] = ((unsigned long long)__float_as_uint(d2c) << 32)
                                | (unsigned)j;
                int b = min(NBIN - 1, (int)(d2c * ((float)NBIN / 145.0f)));
                atomicAdd(&hist[b], 1);
            }
        }
    }
    __syncthreads();
    int nc = min(ncand, MAXC);

    if (nc <= KNBR) {
        if (tid < KNBR) sel[tid] = (tid < nc) ? cand[tid] : U64MAX;
        __syncthreads();
    } else {
        if (tid == 0) {
            int c = 0, B = NBIN - 1;
            for (int b = 0; b < NBIN; b++) {
                if (c + hist[b] >= KNBR) { B = b; break; }
                c += hist[b];
            }
            s_B = B;
        }
        __syncthreads();
        int B = s_B;
        for (int idx = tid; idx < nc; idx += 256) {
            unsigned long long key = cand[idx];
            float d2 = __uint_as_float((unsigned)(key >> 32));
            int b = min(NBIN - 1, (int)(d2 * ((float)NBIN / 145.0f)));
            if (b < B) {
                sel[atomicAdd(&nsel, 1)] = key;
            } else if (b == B) {
                int pp = atomicAdd(&nbin, 1);
                if (pp < BINCAP) binbuf[pp] = key;
            }
        }
        __syncthreads();
        if (tid == 0) {
            int have = nsel;
            int m = KNBR - have;
            int bc = min(nbin, BINCAP);
            for (int s = 0; s < m; s++) {
                unsigned long long best = U64MAX;
                int bi = -1;
                for (int t = 0; t < bc; t++)
                    if (binbuf[t] < best) { best = binbuf[t]; bi = t; }
                if (bi >= 0) binbuf[bi] = U64MAX;
                sel[have + s] = best;
            }
        }
        __syncthreads();
    }

    // --- phase D: warp-0 bitonic sort + write ---
    if (tid < 32) {
        unsigned long long v = sel[tid];
        #pragma unroll
        for (int k = 2; k <= 32; k <<= 1) {
            #pragma unroll
            for (int j = k >> 1; j > 0; j >>= 1) {
                unsigned long long o = __shfl_xor_sync(0xffffffffu, v, j);
                bool up = ((tid & k) == 0);
                bool lower = ((tid & j) == 0);
                unsigned long long mn = min(v, o), mx = max(v, o);
                v = (up == lower) ? mn : mx;
            }
        }
        if (v == U64MAX) {
            g_nbr[i * KNBR + tid] = 0;
            g_dedge[i * KNBR + tid] = BIGD;
        } else {
            g_nbr[i * KNBR + tid] = (int)(v & 0xFFFFFFFFull);
            float d2 = __uint_as_float((unsigned)(v >> 32));
            g_dedge[i * KNBR + tid] = sqrtf(fmaxf(d2, 1e-12f));
        }
    }
}

// ---------------- kernel 5: per-edge messages (R7 version) ----------------
__global__ void __launch_bounds__(256) k_msg(const float* __restrict__ b1) {
    int i = blockIdx.x, tid = threadIdx.x;
    if (!g_valid[i]) {
        g_S[(size_t)i * HID + tid] = 0.0f;
        if (tid == 0) g_cnt[i] = 0;
        return;
    }
    __shared__ float Rs[KNBR * NRBF];
    __shared__ float part[8 * HID];
    __shared__ int   nbr_s[KNBR];
    __shared__ float de_s[KNBR];
    if (tid < KNBR) {
        nbr_s[tid] = g_nbr[i * KNBR + tid];
        de_s[tid]  = g_dedge[i * KNBR + tid];
    }
    __syncthreads();
    for (int idx = tid; idx < KNBR * NRBF; idx += 256) {
        int e = idx >> 6, r = idx & 63;
        float cr = (float)r * RBF_STEP;
        float t = (de_s[e] - cr) * (1.0f / RBF_W);
        float t2 = t * t;
        Rs[idx] = (t2 < 32.0f) ? __expf(-0.5f * t2) : 0.0f;
    }
    if (tid == 0) {
        int c = 0;
        for (int e = 0; e < KNBR; e++) if (de_s[e] <= CUTOFF) c++;
        g_cnt[i] = c;
    }
    __syncthreads();

    int w = tid >> 5, l = tid & 31;
    int zi = g_z[i];
    const float4* ei  = (const float4*)(g_eW1 + zi * HID);
    const float4* b14 = (const float4*)b1;

    float4 a0[4], a1[4];
    #pragma unroll
    for (int rr = 0; rr < 4; rr++) {
        int zn = g_z[nbr_s[4 * w + rr]];
        const float4* en = (const float4*)(g_eW1 + zn * HID);
        float4 u = ei[l], v = en[l], bb = b14[l];
        a0[rr] = make_float4(u.x + v.x + bb.x, u.y + v.y + bb.y,
                             u.z + v.z + bb.z, u.w + v.w + bb.w);
        u = ei[32 + l]; v = en[32 + l]; bb = b14[32 + l];
        a1[rr] = make_float4(u.x + v.x + bb.x, u.y + v.y + bb.y,
                             u.z + v.z + bb.z, u.w + v.w + bb.w);
    }

    float dmin = 3e38f, dmax = -1.0f;
    #pragma unroll
    for (int rr = 0; rr < 4; rr++) {
        float d = de_s[4 * w + rr];
        if (d <= CUTOFF) { dmin = fminf(dmin, d); dmax = fmaxf(dmax, d); }
    }
    if (dmax >= 0.0f) {
        int kmin = max(0,  (int)ceilf ((dmin - 1.0607f) * (1.0f / RBF_STEP)));
        int kmax = min(63, (int)floorf((dmax + 1.0607f) * (1.0f / RBF_STEP)));
        const float* rs_w = Rs + (4 * w) * NRBF;
        for (int k = kmin; k <= kmax; k++) {
            float rv0 = rs_w[k];
            float rv1 = rs_w[NRBF + k];
            float rv2 = rs_w[2 * NRBF + k];
            float rv3 = rs_w[3 * NRBF + k];
            const float4* wr = (const float4*)(g_WW + k * HID);
            float4 w0 = wr[l], w1v = wr[32 + l];
            a0[0].x += rv0 * w0.x;  a0[0].y += rv0 * w0.y;
            a0[0].z += rv0 * w0.z;  a0[0].w += rv0 * w0.w;
            a1[0].x += rv0 * w1v.x; a1[0].y += rv0 * w1v.y;
            a1[0].z += rv0 * w1v.z; a1[0].w += rv0 * w1v.w;
            a0[1].x += rv1 * w0.x;  a0[1].y += rv1 * w0.y;
            a0[1].z += rv1 * w0.z;  a0[1].w += rv1 * w0.w;
            a1[1].x += rv1 * w1v.x; a1[1].y += rv1 * w1v.y;
            a1[1].z += rv1 * w1v.z; a1[1].w += rv1 * w1v.w;
            a0[2].x += rv2 * w0.x;  a0[2].y += rv2 * w0.y;
            a0[2].z += rv2 * w0.z;  a0[2].w += rv2 * w0.w;
            a1[2].x += rv2 * w1v.x; a1[2].y += rv2 * w1v.y;
            a1[2].z += rv2 * w1v.z; a1[2].w += rv2 * w1v.w;
            a0[3].x += rv3 * w0.x;  a0[3].y += rv3 * w0.y;
            a0[3].z += rv3 * w0.z;  a0[3].w += rv3 * w0.w;
            a1[3].x += rv3 * w1v.x; a1[3].y += rv3 * w1v.y;
            a1[3].z += rv3 * w1v.z; a1[3].w += rv3 * w1v.w;
        }
    }

    float4 c0 = make_float4(0, 0, 0, 0), c1 = make_float4(0, 0, 0, 0);
    #pragma unroll
    for (int rr = 0; rr < 4; rr++) {
        if (de_s[4 * w + rr] <= CUTOFF) {
            c0.x += __fdividef(a0[rr].x, 1.0f + __expf(-a0[rr].x));
            c0.y += __fdividef(a0[rr].y, 1.0f + __expf(-a0[rr].y));
            c0.z += __fdividef(a0[rr].z, 1.0f + __expf(-a0[rr].z));
            c0.w += __fdividef(a0[rr].w, 1.0f + __expf(-a0[rr].w));
            c1.x += __fdividef(a1[rr].x, 1.0f + __expf(-a1[rr].x));
            c1.y += __fdividef(a1[rr].y, 1.0f + __expf(-a1[rr].y));
            c1.z += __fdividef(a1[rr].z, 1.0f + __expf(-a1[rr].z));
            c1.w += __fdividef(a1[rr].w, 1.0f + __expf(-a1[rr].w));
        }
    }
    ((float4*)(part + w * HID))[l]      = c0;
    ((float4*)(part + w * HID))[32 + l] = c1;
    __syncthreads();
    float s = 0.0f;
    #pragma unroll
    for (int ww = 0; ww < 8; ww++) s += part[ww * HID + tid];
    g_S[(size_t)i * HID + tid] = s;
}

// ---------------- kernel 6: feat = h + S@W2 + cnt*b2, plus masks ----------------
__global__ void __launch_bounds__(256) k_final(const float* __restrict__ embed,
                                               const float* __restrict__ W2,
                                               const float* __restrict__ b2,
                                               float* __restrict__ out,
                                               int out_size) {
    int base = blockIdx.x * 32;
    int tid = threadIdx.x, w = tid >> 5, l = tid & 31;
    __shared__ float Ssm[32 * HID];
    for (int idx = tid; idx < 32 * HID; idx += 256)
        Ssm[idx] = g_S[(size_t)(base + (idx >> 8)) * HID + (idx & 255)];
    __syncthreads();

    float4 y0[4], y1[4];
    #pragma unroll
    for (int rr = 0; rr < 4; rr++) {
        y0[rr] = make_float4(0, 0, 0, 0);
        y1[rr] = make_float4(0, 0, 0, 0);
    }
    #pragma unroll 4
    for (int k = 0; k < HID; k++) {
        const float4* w2row = (const float4*)(W2 + k * HID);
        float4 wa = w2row[l], wb = w2row[32 + l];
        #pragma unroll
        for (int rr = 0; rr < 4; rr++) {
            float sv = Ssm[(4 * w + rr) * HID + k];
            y0[rr].x += sv * wa.x; y0[rr].y += sv * wa.y;
            y0[rr].z += sv * wa.z; y0[rr].w += sv * wa.w;
            y1[rr].x += sv * wb.x; y1[rr].y += sv * wb.y;
            y1[rr].z += sv * wb.z; y1[rr].w += sv * wb.w;
        }
    }
    const float4* b24 = (const float4*)b2;
    float4 ba = b24[l], bb = b24[32 + l];
    #pragma unroll
    for (int rr = 0; rr < 4; rr++) {
        int n = base + 4 * w + rr;
        int valid = g_valid[n];
        float cnt = (float)g_cnt[n];
        const float4* e4 = (const float4*)(embed + (size_t)g_z[n] * HID);
        float4 ea = e4[l], eb = e4[32 + l];
        float4 oa = make_float4(0, 0, 0, 0), ob = make_float4(0, 0, 0, 0);
        if (valid) {
            oa = make_float4(ea.x + y0[rr].x + cnt * ba.x,
                             ea.y + y0[rr].y + cnt * ba.y,
                             ea.z + y0[rr].z + cnt * ba.z,
                             ea.w + y0[rr].w + cnt * ba.w);
            ob = make_float4(eb.x + y1[rr].x + cnt * bb.x,
                             eb.y + y1[rr].y + cnt * bb.y,
                             eb.z + y1[rr].z + cnt * bb.z,
                             eb.w + y1[rr].w + cnt * bb.w);
        }
        ((float4*)(out + (size_t)n * HID))[l]      = oa;
        ((float4*)(out + (size_t)n * HID))[32 + l] = ob;
    }
    if (tid < 32 && out_size >= N_TOT * HID + 2 * N_TOT) {
        int n = base + tid;
        out[N_TOT * HID + n] = (n >= N_ATOMS && g_valid[n]) ? 1.0f : 0.0f;
        out[N_TOT * HID + N_TOT + n] = (n < N_ATOMS) ? 1.0f : 0.0f;
    }
}

// ---------------- launcher ----------------
extern "C" void kernel_launch(void* const* d_in, const int* in_sizes, int n_in,
                              void* d_out, int out_size) {
    const float* pos   = (const float*)d_in[0];
    const int*   an    = (const int*)  d_in[1];
    const float* cell  = (const float*)d_in[2];
    const float* embed = (const float*)d_in[3];
    const float* Wrbf  = (const float*)d_in[4];
    const float* W1    = (const float*)d_in[5];
    const float* b1    = (const float*)d_in[6];
    const float* W2    = (const float*)d_in[7];
    const float* b2    = (const float*)d_in[8];
    float* out = (float*)d_out;

    k_setup<<<(N_TOT + 255) / 256, 256>>>(pos, an, cell);
    k_cellbuild<<<1, NCELL3>>>();
    k_vmask<<<N_GRID, 256>>>();
    k_pre<<<NEMB + NRBF, 256>>>(embed, Wrbf, W1);
    k_topk<<<N_TOT, 256>>>();
    k_msg<<<N_TOT, 256>>>(b1);
    k_final<<<N_TOT / 32, 256>>>(embed, W2, b2, out, out_size);
}

// round 10
// speedup vs baseline: 1.2207x; 1.0209x over previous
#include <cuda_runtime.h>
#include <math.h>

#define N_ATOMS 4096
#define NG      12
#define N_GRID  1728
#define N_TOT   5824
#define HID     256
#define KNBR    32
#define NRBF    64
#define CUTOFF  12.0f
#define RBF_W   (CUTOFF / (float)NRBF)
#define RBF_STEP (CUTOFF / 63.0f)
#define BIGD    1e9f
#define VNODE_Z 120
#define NEMB    125
#define MAXC    1536
#define NBIN    128
#define BINCAP  256
#define U64MAX  0xFFFFFFFFFFFFFFFFull
#define NCELL   8
#define NCELL3  512
#define CSIZE   5.0f

// ---------------- device scratch ----------------
__device__ float4 g_pos4[N_TOT];
__device__ int    g_valid[N_TOT];
__device__ int    g_z[N_TOT];
__device__ int    g_nbr[N_TOT * KNBR];
__device__ float  g_dedge[N_TOT * KNBR];
__device__ float  g_eW1[NEMB * HID];
__device__ float  g_WW[NRBF * HID];
__device__ float  g_S[N_TOT * HID];
__device__ int    g_cnt[N_TOT];
__device__ int    g_cellcnt[NCELL3];
__device__ int    g_cellstart[NCELL3];
__device__ int    g_cellnodes[N_TOT];

__device__ __forceinline__ int cell_of(float x, float y, float z) {
    int ix = min(NCELL - 1, max(0, (int)(x / CSIZE)));
    int iy = min(NCELL - 1, max(0, (int)(y / CSIZE)));
    int iz = min(NCELL - 1, max(0, (int)(z / CSIZE)));
    return (ix * NCELL + iy) * NCELL + iz;
}

__device__ __forceinline__ float cell_mind2(int c, float px, float py, float pz) {
    int ix = c / (NCELL * NCELL), iy = (c / NCELL) % NCELL, iz = c % NCELL;
    float lx = ix * CSIZE, ly = iy * CSIZE, lz = iz * CSIZE;
    float dx = fmaxf(0.0f, fmaxf(lx - px, px - (lx + CSIZE)));
    float dy = fmaxf(0.0f, fmaxf(ly - py, py - (ly + CSIZE)));
    float dz = fmaxf(0.0f, fmaxf(lz - pz, pz - (lz + CSIZE)));
    return dx * dx + dy * dy + dz * dz;
}

// ---------------- kernel 1: setup ----------------
__global__ void k_setup(const float* __restrict__ pos,
                        const int* __restrict__ an,
                        const float* __restrict__ cell) {
    int i = blockIdx.x * blockDim.x + threadIdx.x;
    if (i >= N_TOT) return;
    float x, y, z;
    if (i < N_ATOMS) {
        x = pos[3 * i + 0]; y = pos[3 * i + 1]; z = pos[3 * i + 2];
        g_valid[i] = 1;
        g_z[i] = an[i];
    } else {
        int g = i - N_ATOMS;
        int ix = g / (NG * NG), iy = (g / NG) % NG, iz = g % NG;
        float f0 = (float)ix / (float)NG;
        float f1 = (float)iy / (float)NG;
        float f2 = (float)iz / (float)NG;
        x = f0 * cell[0] + f1 * cell[3] + f2 * cell[6];
        y = f0 * cell[1] + f1 * cell[4] + f2 * cell[7];
        z = f0 * cell[2] + f1 * cell[5] + f2 * cell[8];
        g_z[i] = VNODE_Z;
    }
    g_pos4[i] = make_float4(x, y, z, x * x + y * y + z * z);
}

// ---------------- single block: count + scan + scatter ----------------
__global__ void __launch_bounds__(NCELL3) k_cellbuild() {
    __shared__ int cnt[NCELL3];
    __shared__ int tmp[NCELL3];
    __shared__ int fill[NCELL3];
    int t = threadIdx.x;
    cnt[t] = 0;
    __syncthreads();
    for (int i = t; i < N_TOT; i += NCELL3) {
        float4 p = g_pos4[i];
        atomicAdd(&cnt[cell_of(p.x, p.y, p.z)], 1);
    }
    __syncthreads();
    int v = cnt[t];
    tmp[t] = v;
    __syncthreads();
    for (int off = 1; off < NCELL3; off <<= 1) {
        int x = (t >= off) ? tmp[t - off] : 0;
        __syncthreads();
        tmp[t] += x;
        __syncthreads();
    }
    int excl = tmp[t] - v;
    g_cellstart[t] = excl;
    g_cellcnt[t] = v;
    fill[t] = excl;
    __syncthreads();
    for (int i = t; i < N_TOT; i += NCELL3) {
        float4 p = g_pos4[i];
        int pp = atomicAdd(&fill[cell_of(p.x, p.y, p.z)], 1);
        g_cellnodes[pp] = i;
    }
}

// ---------------- kernel 2: vnode repulsion mask ----------------
__global__ void __launch_bounds__(256) k_vmask() {
    int i = N_ATOMS + blockIdx.x;
    int tid = threadIdx.x, w = tid >> 5, lane = tid & 31;
    __shared__ int pcell[64];
    __shared__ int npass_s;
    __shared__ float wm[8];
    if (tid == 0) npass_s = 0;
    __syncthreads();
    float4 p = g_pos4[i];
    for (int c = tid; c < NCELL3; c += 256) {
        if (g_cellcnt[c] > 0 && cell_mind2(c, p.x, p.y, p.z) <= 4.01f) {
            int q = atomicAdd(&npass_s, 1);
            if (q < 64) pcell[q] = c;
        }
    }
    __syncthreads();
    int np = min(npass_s, 64);
    float m = 3e38f;
    for (int q = w; q < np; q += 8) {
        int pc = pcell[q];
        int st = g_cellstart[pc], cnt = g_cellcnt[pc];
        for (int t = lane; t < cnt; t += 32) {
            int j = g_cellnodes[st + t];
            if (j < N_ATOMS) {
                float4 qq = g_pos4[j];
                float d2 = p.w + qq.w - 2.0f * (p.x * qq.x + p.y * qq.y + p.z * qq.z);
                m = fminf(m, d2);
            }
        }
    }
    #pragma unroll
    for (int o = 16; o; o >>= 1) m = fminf(m, __shfl_xor_sync(0xffffffffu, m, o));
    if (lane == 0) wm[w] = m;
    __syncthreads();
    if (tid == 0) {
        float b = wm[0];
        #pragma unroll
        for (int ww = 1; ww < 8; ww++) b = fminf(b, wm[ww]);
        g_valid[i] = (b >= 4.0f) ? 1 : 0;
    }
}

// ---------------- kernel 3: precompute, K split 4 ways per block ----------------
// 1024 threads: col c = tid&255, k-quarter kq = tid>>8. Partials combined in
// fixed order -> deterministic.
__global__ void __launch_bounds__(1024) k_pre(const float* __restrict__ embed,
                                              const float* __restrict__ Wrbf,
                                              const float* __restrict__ W1) {
    int r = blockIdx.x;
    int tid = threadIdx.x;
    int c = tid & 255, kq = tid >> 8;
    const float* A = (r < NEMB) ? (embed + (size_t)r * HID)
                                : (Wrbf + (size_t)(r - NEMB) * HID);
    __shared__ float As[HID];
    __shared__ float part[4][HID];
    if (tid < HID) As[tid] = A[tid];
    __syncthreads();
    int k0 = kq * 64;
    float a0 = 0.f, a1 = 0.f, a2 = 0.f, a3 = 0.f;
    float a4 = 0.f, a5 = 0.f, a6 = 0.f, a7 = 0.f;
    #pragma unroll
    for (int k = k0; k < k0 + 64; k += 8) {
        a0 += As[k + 0] * W1[(k + 0) * HID + c];
        a1 += As[k + 1] * W1[(k + 1) * HID + c];
        a2 += As[k + 2] * W1[(k + 2) * HID + c];
        a3 += As[k + 3] * W1[(k + 3) * HID + c];
        a4 += As[k + 4] * W1[(k + 4) * HID + c];
        a5 += As[k + 5] * W1[(k + 5) * HID + c];
        a6 += As[k + 6] * W1[(k + 6) * HID + c];
        a7 += As[k + 7] * W1[(k + 7) * HID + c];
    }
    part[kq][c] = ((a0 + a1) + (a2 + a3)) + ((a4 + a5) + (a6 + a7));
    __syncthreads();
    if (kq == 0) {
        float acc = (part[0][c] + part[1][c]) + (part[2][c] + part[3][c]);
        if (r < NEMB) g_eW1[r * HID + c] = acc;
        else          g_WW[(r - NEMB) * HID + c] = acc;
    }
}

// ---------------- kernel 4: top-K via contiguous z-column ranges ----------------
__global__ void __launch_bounds__(256) k_topk() {
    int i = blockIdx.x, tid = threadIdx.x;
    int w = tid >> 5, lane = tid & 31;
    __shared__ unsigned long long cand[MAXC];
    __shared__ unsigned long long binbuf[BINCAP];
    __shared__ unsigned long long sel[KNBR];
    __shared__ int hist[NBIN];
    __shared__ int rs[64], rl[64];
    __shared__ int ncand, nsel, nbin, s_B, nrange;
    if (!g_valid[i]) {
        if (tid < KNBR) { g_nbr[i * KNBR + tid] = 0; g_dedge[i * KNBR + tid] = BIGD; }
        return;
    }
    if (tid == 0) { ncand = 0; nsel = 0; nbin = 0; nrange = 0; }
    if (tid < NBIN) hist[tid] = 0;
    __syncthreads();

    float4 p = g_pos4[i];

    if (tid < 64) {
        int ix = tid >> 3, iy = tid & 7;
        float lx = ix * CSIZE, ly = iy * CSIZE;
        float dx = fmaxf(0.0f, fmaxf(lx - p.x, p.x - (lx + CSIZE)));
        float dy = fmaxf(0.0f, fmaxf(ly - p.y, p.y - (ly + CSIZE)));
        float dxy2 = dx * dx + dy * dy;
        if (dxy2 <= 145.5f) {
            float rem = sqrtf(145.5f - dxy2);
            int z0 = max(0,         (int)floorf((p.z - rem) * (1.0f / CSIZE)));
            int z1 = min(NCELL - 1, (int)floorf((p.z + rem) * (1.0f / CSIZE)));
            int c0 = tid * NCELL + z0, c1 = tid * NCELL + z1;
            int st = g_cellstart[c0];
            int en = g_cellstart[c1] + g_cellcnt[c1];
            if (en > st) {
                int q = atomicAdd(&nrange, 1);
                rs[q] = st; rl[q] = en - st;
            }
        }
    }
    __syncthreads();
    int np = nrange;

    for (int q = w; q < np; q += 8) {
        int st = rs[q], len = rl[q];
        int cr = (len + 31) & ~31;
        for (int t = lane; t < cr; t += 32) {
            bool keep = false;
            float d2 = 0.0f;
            int j = -1;
            if (t < len) {
                j = g_cellnodes[st + t];
                float4 qq = g_pos4[j];
                d2 = p.w + qq.w - 2.0f * (p.x * qq.x + p.y * qq.y + p.z * qq.z);
                keep = (d2 <= 145.0f) && (j != i) && (g_valid[j] != 0);
            }
            unsigned m = __ballot_sync(0xffffffffu, keep);
            int cpos = 0;
            if (lane == 0) cpos = m ? atomicAdd(&ncand, __popc(m)) : 0;
            cpos = __shfl_sync(0xffffffffu, cpos, 0);
            if (keep) {
                float d2c = fmaxf(d2, 0.0f);
                int off = cpos + __popc(m & ((1u << lane) - 1u));
                if (off < MAXC)
                    cand[off] = ((unsigned long long)__float_as_uint(d2c) << 32)
                                | (unsigned)j;
                int b = min(NBIN - 1, (int)(d2c * ((float)NBIN / 145.0f)));
                atomicAdd(&hist[b], 1);
            }
        }
    }
    __syncthreads();
    int nc = min(ncand, MAXC);

    if (nc <= KNBR) {
        if (tid < KNBR) sel[tid] = (tid < nc) ? cand[tid] : U64MAX;
        __syncthreads();
    } else {
        if (tid == 0) {
            int c = 0, B = NBIN - 1;
            for (int b = 0; b < NBIN; b++) {
                if (c + hist[b] >= KNBR) { B = b; break; }
                c += hist[b];
            }
            s_B = B;
        }
        __syncthreads();
        int B = s_B;
        for (int idx = tid; idx < nc; idx += 256) {
            unsigned long long key = cand[idx];
            float d2 = __uint_as_float((unsigned)(key >> 32));
            int b = min(NBIN - 1, (int)(d2 * ((float)NBIN / 145.0f)));
            if (b < B) {
                sel[atomicAdd(&nsel, 1)] = key;
            } else if (b == B) {
                int pp = atomicAdd(&nbin, 1);
                if (pp < BINCAP) binbuf[pp] = key;
            }
        }
        __syncthreads();
        if (tid == 0) {
            int have = nsel;
            int m = KNBR - have;
            int bc = min(nbin, BINCAP);
            for (int s = 0; s < m; s++) {
                unsigned long long best = U64MAX;
                int bi = -1;
                for (int t = 0; t < bc; t++)
                    if (binbuf[t] < best) { best = binbuf[t]; bi = t; }
                if (bi >= 0) binbuf[bi] = U64MAX;
                sel[have + s] = best;
            }
        }
        __syncthreads();
    }

    if (tid < 32) {
        unsigned long long v = sel[tid];
        #pragma unroll
        for (int k = 2; k <= 32; k <<= 1) {
            #pragma unroll
            for (int j = k >> 1; j > 0; j >>= 1) {
                unsigned long long o = __shfl_xor_sync(0xffffffffu, v, j);
                bool up = ((tid & k) == 0);
                bool lower = ((tid & j) == 0);
                unsigned long long mn = min(v, o), mx = max(v, o);
                v = (up == lower) ? mn : mx;
            }
        }
        if (v == U64MAX) {
            g_nbr[i * KNBR + tid] = 0;
            g_dedge[i * KNBR + tid] = BIGD;
        } else {
            g_nbr[i * KNBR + tid] = (int)(v & 0xFFFFFFFFull);
            float d2 = __uint_as_float((unsigned)(v >> 32));
            g_dedge[i * KNBR + tid] = sqrtf(fmaxf(d2, 1e-12f));
        }
    }
}

// ---------------- kernel 5: per-edge messages ----------------
__global__ void __launch_bounds__(256) k_msg(const float* __restrict__ b1) {
    int i = blockIdx.x, tid = threadIdx.x;
    if (!g_valid[i]) {
        g_S[(size_t)i * HID + tid] = 0.0f;
        if (tid == 0) g_cnt[i] = 0;
        return;
    }
    __shared__ float Rs[KNBR * NRBF];
    __shared__ float part[8 * HID];
    __shared__ int   nbr_s[KNBR];
    __shared__ float de_s[KNBR];
    if (tid < KNBR) {
        nbr_s[tid] = g_nbr[i * KNBR + tid];
        de_s[tid]  = g_dedge[i * KNBR + tid];
    }
    __syncthreads();
    for (int idx = tid; idx < KNBR * NRBF; idx += 256) {
        int e = idx >> 6, r = idx & 63;
        float cr = (float)r * RBF_STEP;
        float t = (de_s[e] - cr) * (1.0f / RBF_W);
        float t2 = t * t;
        Rs[idx] = (t2 < 32.0f) ? __expf(-0.5f * t2) : 0.0f;
    }
    if (tid == 0) {
        int c = 0;
        for (int e = 0; e < KNBR; e++) if (de_s[e] <= CUTOFF) c++;
        g_cnt[i] = c;
    }
    __syncthreads();

    int w = tid >> 5, l = tid & 31;
    int zi = g_z[i];
    const float4* ei  = (const float4*)(g_eW1 + zi * HID);
    const float4* b14 = (const float4*)b1;

    float4 a0[4], a1[4];
    #pragma unroll
    for (int rr = 0; rr < 4; rr++) {
        int zn = g_z[nbr_s[4 * w + rr]];
        const float4* en = (const float4*)(g_eW1 + zn * HID);
        float4 u = ei[l], v = en[l], bb = b14[l];
        a0[rr] = make_float4(u.x + v.x + bb.x, u.y + v.y + bb.y,
                             u.z + v.z + bb.z, u.w + v.w + bb.w);
        u = ei[32 + l]; v = en[32 + l]; bb = b14[32 + l];
        a1[rr] = make_float4(u.x + v.x + bb.x, u.y + v.y + bb.y,
                             u.z + v.z + bb.z, u.w + v.w + bb.w);
    }

    float dmin = 3e38f, dmax = -1.0f;
    #pragma unroll
    for (int rr = 0; rr < 4; rr++) {
        float d = de_s[4 * w + rr];
        if (d <= CUTOFF) { dmin = fminf(dmin, d); dmax = fmaxf(dmax, d); }
    }
    if (dmax >= 0.0f) {
        int kmin = max(0,  (int)ceilf ((dmin - 1.0607f) * (1.0f / RBF_STEP)));
        int kmax = min(63, (int)floorf((dmax + 1.0607f) * (1.0f / RBF_STEP)));
        const float* rs_w = Rs + (4 * w) * NRBF;
        for (int k = kmin; k <= kmax; k++) {
            float rv0 = rs_w[k];
            float rv1 = rs_w[NRBF + k];
            float rv2 = rs_w[2 * NRBF + k];
            float rv3 = rs_w[3 * NRBF + k];
            const float4* wr = (const float4*)(g_WW + k * HID);
            float4 w0 = wr[l], w1v = wr[32 + l];
            a0[0].x += rv0 * w0.x;  a0[0].y += rv0 * w0.y;
            a0[0].z += rv0 * w0.z;  a0[0].w += rv0 * w0.w;
            a1[0].x += rv0 * w1v.x; a1[0].y += rv0 * w1v.y;
            a1[0].z += rv0 * w1v.z; a1[0].w += rv0 * w1v.w;
            a0[1].x += rv1 * w0.x;  a0[1].y += rv1 * w0.y;
            a0[1].z += rv1 * w0.z;  a0[1].w += rv1 * w0.w;
            a1[1].x += rv1 * w1v.x; a1[1].y += rv1 * w1v.y;
            a1[1].z += rv1 * w1v.z; a1[1].w += rv1 * w1v.w;
            a0[2].x += rv2 * w0.x;  a0[2].y += rv2 * w0.y;
            a0[2].z += rv2 * w0.z;  a0[2].w += rv2 * w0.w;
            a1[2].x += rv2 * w1v.x; a1[2].y += rv2 * w1v.y;
            a1[2].z += rv2 * w1v.z; a1[2].w += rv2 * w1v.w;
            a0[3].x += rv3 * w0.x;  a0[3].y += rv3 * w0.y;
            a0[3].z += rv3 * w0.z;  a0[3].w += rv3 * w0.w;
            a1[3].x += rv3 * w1v.x; a1[3].y += rv3 * w1v.y;
            a1[3].z += rv3 * w1v.z; a1[3].w += rv3 * w1v.w;
        }
    }

    float4 c0 = make_float4(0, 0, 0, 0), c1 = make_float4(0, 0, 0, 0);
    #pragma unroll
    for (int rr = 0; rr < 4; rr++) {
        if (de_s[4 * w + rr] <= CUTOFF) {
            c0.x += __fdividef(a0[rr].x, 1.0f + __expf(-a0[rr].x));
            c0.y += __fdividef(a0[rr].y, 1.0f + __expf(-a0[rr].y));
            c0.z += __fdividef(a0[rr].z, 1.0f + __expf(-a0[rr].z));
            c0.w += __fdividef(a0[rr].w, 1.0f + __expf(-a0[rr].w));
            c1.x += __fdividef(a1[rr].x, 1.0f + __expf(-a1[rr].x));
            c1.y += __fdividef(a1[rr].y, 1.0f + __expf(-a1[rr].y));
            c1.z += __fdividef(a1[rr].z, 1.0f + __expf(-a1[rr].z));
            c1.w += __fdividef(a1[rr].w, 1.0f + __expf(-a1[rr].w));
        }
    }
    ((float4*)(part + w * HID))[l]      = c0;
    ((float4*)(part + w * HID))[32 + l] = c1;
    __syncthreads();
    float s = 0.0f;
    #pragma unroll
    for (int ww = 0; ww < 8; ww++) s += part[ww * HID + tid];
    g_S[(size_t)i * HID + tid] = s;
}

// ---------------- kernel 6: feat = h + S@W2 + cnt*b2, plus masks ----------------
__global__ void __launch_bounds__(256) k_final(const float* __restrict__ embed,
                                               const float* __restrict__ W2,
                                               const float* __restrict__ b2,
                                               float* __restrict__ out,
                                               int out_size) {
    int base = blockIdx.x * 32;
    int tid = threadIdx.x, w = tid >> 5, l = tid & 31;
    __shared__ float Ssm[32 * HID];
    for (int idx = tid; idx < 32 * HID; idx += 256)
        Ssm[idx] = g_S[(size_t)(base + (idx >> 8)) * HID + (idx & 255)];
    __syncthreads();

    float4 y0[4], y1[4];
    #pragma unroll
    for (int rr = 0; rr < 4; rr++) {
        y0[rr] = make_float4(0, 0, 0, 0);
        y1[rr] = make_float4(0, 0, 0, 0);
    }
    #pragma unroll 4
    for (int k = 0; k < HID; k++) {
        const float4* w2row = (const float4*)(W2 + k * HID);
        float4 wa = w2row[l], wb = w2row[32 + l];
        #pragma unroll
        for (int rr = 0; rr < 4; rr++) {
            float sv = Ssm[(4 * w + rr) * HID + k];
            y0[rr].x += sv * wa.x; y0[rr].y += sv * wa.y;
            y0[rr].z += sv * wa.z; y0[rr].w += sv * wa.w;
            y1[rr].x += sv * wb.x; y1[rr].y += sv * wb.y;
            y1[rr].z += sv * wb.z; y1[rr].w += sv * wb.w;
        }
    }
    const float4* b24 = (const float4*)b2;
    float4 ba = b24[l], bb = b24[32 + l];
    #pragma unroll
    for (int rr = 0; rr < 4; rr++) {
        int n = base + 4 * w + rr;
        int valid = g_valid[n];
        float cnt = (float)g_cnt[n];
        const float4* e4 = (const float4*)(embed + (size_t)g_z[n] * HID);
        float4 ea = e4[l], eb = e4[32 + l];
        float4 oa = make_float4(0, 0, 0, 0), ob = make_float4(0, 0, 0, 0);
        if (valid) {
            oa = make_float4(ea.x + y0[rr].x + cnt * ba.x,
                             ea.y + y0[rr].y + cnt * ba.y,
                             ea.z + y0[rr].z + cnt * ba.z,
                             ea.w + y0[rr].w + cnt * ba.w);
            ob = make_float4(eb.x + y1[rr].x + cnt * bb.x,
                             eb.y + y1[rr].y + cnt * bb.y,
                             eb.z + y1[rr].z + cnt * bb.z,
                             eb.w + y1[rr].w + cnt * bb.w);
        }
        ((float4*)(out + (size_t)n * HID))[l]      = oa;
        ((float4*)(out + (size_t)n * HID))[32 + l] = ob;
    }
    if (tid < 32 && out_size >= N_TOT * HID + 2 * N_TOT) {
        int n = base + tid;
        out[N_TOT * HID + n] = (n >= N_ATOMS && g_valid[n]) ? 1.0f : 0.0f;
        out[N_TOT * HID + N_TOT + n] = (n < N_ATOMS) ? 1.0f : 0.0f;
    }
}

// ---------------- launcher ----------------
extern "C" void kernel_launch(void* const* d_in, const int* in_sizes, int n_in,
                              void* d_out, int out_size) {
    const float* pos   = (const float*)d_in[0];
    const int*   an    = (const int*)  d_in[1];
    const float* cell  = (const float*)d_in[2];
    const float* embed = (const float*)d_in[3];
    const float* Wrbf  = (const float*)d_in[4];
    const float* W1    = (const float*)d_in[5];
    const float* b1    = (const float*)d_in[6];
    const float* W2    = (const float*)d_in[7];
    const float* b2    = (const float*)d_in[8];
    float* out = (float*)d_out;

    k_setup<<<(N_TOT + 255) / 256, 256>>>(pos, an, cell);
    k_cellbuild<<<1, NCELL3>>>();
    k_vmask<<<N_GRID, 256>>>();
    k_pre<<<NEMB + NRBF, 1024>>>(embed, Wrbf, W1);
    k_topk<<<N_TOT, 256>>>();
    k_msg<<<N_TOT, 256>>>(b1);
    k_final<<<N_TOT / 32, 256>>>(embed, W2, b2, out, out_size);
}